// round 6
// baseline (speedup 1.0000x reference)
#include <cuda_runtime.h>
#include <cuda_bf16.h>
#include <math.h>

// Problem constants
#define B_   8
#define NQ_  1024
#define C_   256
#define S_   21504
#define BNQ  (B_*NQ_)      // 8192 rows
#define BS_  (B_*S_)       // 172032 rows

// ---------------- device scratch (no allocations allowed) ----------------
__device__ float g_q   [BNQ*C_];
__device__ float g_qkv [BNQ*3*C_];
__device__ float g_attn[BNQ*C_];
__device__ float g_tgt2[BNQ*C_];
__device__ float g_tgt3[BNQ*C_];
__device__ __nv_bfloat16 g_valh[BS_*(size_t)C_];   // bf16 value tensor
__device__ __nv_bfloat16 g_memh[BS_*(size_t)C_];   // bf16 copy of memory
__device__ __nv_bfloat16 g_vpwh[C_*C_];            // bf16 vp weights
__device__ float g_so  [BNQ*384];
__device__ float g_aw  [BNQ*192];
__device__ float g_ref [BNQ*2];
__device__ float g_ca  [BNQ*C_];
__device__ float g_ff1 [BNQ*1024];

__device__ __forceinline__ unsigned pack2(float a, float b) {
    __nv_bfloat162 h = __floats2bfloat162_rn(a, b);
    return *(unsigned*)&h;
}

// ---------------- fp32 -> bf16 conversion (grid-stride) ------------------
__global__ void __launch_bounds__(256) cvt2bf16(const float4* __restrict__ in,
                                                uint2* __restrict__ outp, long n4)
{
    long i = blockIdx.x*(long)blockDim.x + threadIdx.x;
    long stride = (long)gridDim.x*blockDim.x;
    for (; i < n4; i += stride) {
        float4 v = in[i];
        uint2 o; o.x = pack2(v.x, v.y); o.y = pack2(v.z, v.w);
        outp[i] = o;
    }
}

// ---------------- LayerNorm: one block (256 thr) per row, C=256 ----------
__global__ void __launch_bounds__(256) ln_kernel(const float* __restrict__ x,
    const float* __restrict__ w, const float* __restrict__ b,
    float* __restrict__ y)
{
    int row = blockIdx.x;
    float v = x[(size_t)row*C_ + threadIdx.x];
    float s = v, s2 = v*v;
    __shared__ float red[16];
    int lane = threadIdx.x & 31, wid = threadIdx.x >> 5;
    #pragma unroll
    for (int o = 16; o; o >>= 1) {
        s  += __shfl_xor_sync(0xffffffffu, s,  o);
        s2 += __shfl_xor_sync(0xffffffffu, s2, o);
    }
    if (lane == 0) { red[wid] = s; red[wid+8] = s2; }
    __syncthreads();
    float ts = 0.f, ts2 = 0.f;
    #pragma unroll
    for (int i = 0; i < 8; i++) { ts += red[i]; ts2 += red[i+8]; }
    float mean = ts * (1.f/C_);
    float var  = ts2 * (1.f/C_) - mean*mean;
    float r = rsqrtf(var + 1e-5f);
    y[(size_t)row*C_ + threadIdx.x] = (v - mean)*r*w[threadIdx.x] + b[threadIdx.x];
}

// ---------------- cp.async helpers ---------------------------------------
__device__ __forceinline__ void cp16(unsigned dst, const void* src, bool pred) {
    int sz = pred ? 16 : 0;
    asm volatile("cp.async.cg.shared.global [%0], [%1], 16, %2;\n"
                 :: "r"(dst), "l"(src), "r"(sz));
}
__device__ __forceinline__ void cp_commit() {
    asm volatile("cp.async.commit_group;\n");
}
__device__ __forceinline__ void cp_wait2() {
    asm volatile("cp.async.wait_group 2;\n");
}

__device__ __forceinline__ void mma_tf32(float* d, const unsigned* a, const unsigned* b) {
    asm volatile(
      "mma.sync.aligned.m16n8k8.row.col.f32.tf32.tf32.f32 "
      "{%0,%1,%2,%3}, {%4,%5,%6,%7}, {%8,%9}, {%0,%1,%2,%3};\n"
      : "+f"(d[0]), "+f"(d[1]), "+f"(d[2]), "+f"(d[3])
      : "r"(a[0]), "r"(a[1]), "r"(a[2]), "r"(a[3]), "r"(b[0]), "r"(b[1]));
}

__device__ __forceinline__ void mma_bf16(float* d, const unsigned* a, const unsigned* b) {
    asm volatile(
      "mma.sync.aligned.m16n8k16.row.col.f32.bf16.bf16.f32 "
      "{%0,%1,%2,%3}, {%4,%5,%6,%7}, {%8,%9}, {%0,%1,%2,%3};\n"
      : "+f"(d[0]), "+f"(d[1]), "+f"(d[2]), "+f"(d[3])
      : "r"(a[0]), "r"(a[1]), "r"(a[2]), "r"(a[3]), "r"(b[0]), "r"(b[1]));
}

// ---------------- TF32 tensor-core GEMM (cp.async 4-stage) ---------------
#define NSTG 4
#define STG_WORDS 5120          // (128*20) A + (128*20) B per stage
#define SMEM_BYTES (NSTG*STG_WORDS*4)

template<int ACT>   // 0 = none, 1 = exact GELU
__global__ void __launch_bounds__(256, 2) gemm_tc(const float* __restrict__ A,
    const float* __restrict__ W, const float* __restrict__ bias,
    const float* __restrict__ res, float* __restrict__ Co,
    int M, int N, int K)
{
    extern __shared__ unsigned sh[];

    const int t    = threadIdx.x;
    const int warp = t >> 5;
    const int lane = t & 31;
    const int grp  = lane >> 2;
    const int t4   = lane & 3;
    const int wm   = warp & 1;
    const int wn   = warp >> 1;
    const int m0   = blockIdx.y * 128, n0 = blockIdx.x * 128;

    const int lrow = t >> 2;
    const int lc4  = (t & 3) * 4;

    const float* Ag0 = A + (size_t)(m0 + lrow     ) * K + lc4;
    const float* Ag1 = Ag0 + (size_t)64 * K;
    const bool wok0 = (n0 + lrow     ) < N;
    const bool wok1 = (n0 + lrow + 64) < N;
    const float* Wg0 = W + (size_t)(wok0 ? (n0 + lrow     ) : 0) * K + lc4;
    const float* Wg1 = W + (size_t)(wok1 ? (n0 + lrow + 64) : 0) * K + lc4;

    const unsigned sbase = (unsigned)__cvta_generic_to_shared(sh);
    const unsigned dA0 = sbase + ((lrow      )*20 + lc4)*4;
    const unsigned dA1 = sbase + ((lrow + 64 )*20 + lc4)*4;
    const unsigned dB0 = sbase + (2560 + (lrow     )*20 + lc4)*4;
    const unsigned dB1 = sbase + (2560 + (lrow + 64)*20 + lc4)*4;

    float acc[4][4][4];
    #pragma unroll
    for (int i = 0; i < 4; i++)
        #pragma unroll
        for (int j = 0; j < 4; j++)
            #pragma unroll
            for (int r = 0; r < 4; r++) acc[i][j][r] = 0.f;

    const int iters = K >> 4;

    #pragma unroll
    for (int s = 0; s < NSTG - 1; s++) {
        unsigned off = s * STG_WORDS * 4;
        int ko = s << 4;
        cp16(dA0 + off, Ag0 + ko, true);
        cp16(dA1 + off, Ag1 + ko, true);
        cp16(dB0 + off, Wg0 + ko, wok0);
        cp16(dB1 + off, Wg1 + ko, wok1);
        cp_commit();
    }

    int s = 0;
    for (int it = 0; it < iters; it++) {
        cp_wait2();
        __syncthreads();

        const unsigned* Asm = sh + s * STG_WORDS;
        const unsigned* Bsm = Asm + 2560;

        #pragma unroll
        for (int kb = 0; kb < 16; kb += 8) {
            unsigned af[4][4], bf[4][2];
            #pragma unroll
            for (int mt = 0; mt < 4; mt++) {
                int m = wm*64 + mt*16 + grp;
                af[mt][0] = Asm[(m  )*20 + kb + t4];
                af[mt][1] = Asm[(m+8)*20 + kb + t4];
                af[mt][2] = Asm[(m  )*20 + kb + t4 + 4];
                af[mt][3] = Asm[(m+8)*20 + kb + t4 + 4];
            }
            #pragma unroll
            for (int nt = 0; nt < 4; nt++) {
                int n = wn*32 + nt*8 + grp;
                bf[nt][0] = Bsm[n*20 + kb + t4];
                bf[nt][1] = Bsm[n*20 + kb + t4 + 4];
            }
            #pragma unroll
            for (int mt = 0; mt < 4; mt++)
                #pragma unroll
                for (int nt = 0; nt < 4; nt++)
                    mma_tf32(acc[mt][nt], af[mt], bf[nt]);
        }

        int kt = it + NSTG - 1;
        if (kt < iters) {
            int sn = s + NSTG - 1; if (sn >= NSTG) sn -= NSTG;
            unsigned off = sn * STG_WORDS * 4;
            int ko = kt << 4;
            cp16(dA0 + off, Ag0 + ko, true);
            cp16(dA1 + off, Ag1 + ko, true);
            cp16(dB0 + off, Wg0 + ko, wok0);
            cp16(dB1 + off, Wg1 + ko, wok1);
        }
        cp_commit();
        if (++s == NSTG) s = 0;
    }

    #pragma unroll
    for (int mt = 0; mt < 4; mt++) {
        #pragma unroll
        for (int nt = 0; nt < 4; nt++) {
            int rbase = m0 + wm*64 + mt*16 + grp;
            int cbase = n0 + wn*32 + nt*8 + t4*2;
            #pragma unroll
            for (int rr = 0; rr < 2; rr++) {
                int m = rbase + rr*8;
                #pragma unroll
                for (int cc = 0; cc < 2; cc++) {
                    int n = cbase + cc;
                    if (n < N) {
                        float v = acc[mt][nt][rr*2 + cc] + bias[n];
                        if (ACT == 1) v = 0.5f*v*(1.f + erff(v*0.70710678118654752f));
                        if (res) v += res[(size_t)m*N + n];
                        Co[(size_t)m*N + n] = v;
                    }
                }
            }
        }
    }
}

// ---------------- bf16 tensor-core GEMM (value projection) ---------------
// C_bf16[M,N] = A_bf16[M,K] @ W_bf16[N,K]^T + bias. BK=32, m16n8k16.
#define BSTG_WORDS 5120          // A 128x20 + B 128x20 (packed bf16 pair words)
#define BSMEM_BYTES (NSTG*BSTG_WORDS*4)

__global__ void __launch_bounds__(256, 2) gemm_bf(const __nv_bfloat16* __restrict__ A,
    const __nv_bfloat16* __restrict__ W, const float* __restrict__ bias,
    __nv_bfloat16* __restrict__ Co, int M, int N, int K)
{
    extern __shared__ unsigned sh[];

    const int t = threadIdx.x, warp = t >> 5, lane = t & 31;
    const int grp = lane >> 2, t4 = lane & 3;
    const int wm = warp & 1, wn = warp >> 1;
    const int m0 = blockIdx.y * 128, n0 = blockIdx.x * 128;

    const int lrow = t >> 1;          // 0..127
    const int lw   = (t & 1) * 8;     // word offset 0 or 8 (16 bf16 elems)

    const __nv_bfloat16* Ag = A + (size_t)(m0 + lrow)*K + lw*2;
    const bool wok = (n0 + lrow) < N;
    const __nv_bfloat16* Wg = W + (size_t)(wok ? (n0 + lrow) : 0)*K + lw*2;

    const unsigned sbase = (unsigned)__cvta_generic_to_shared(sh);
    const unsigned dA = sbase + (lrow*20 + lw)*4;
    const unsigned dB = sbase + (2560 + lrow*20 + lw)*4;

    float acc[4][4][4];
    #pragma unroll
    for (int i = 0; i < 4; i++)
        #pragma unroll
        for (int j = 0; j < 4; j++)
            #pragma unroll
            for (int r = 0; r < 4; r++) acc[i][j][r] = 0.f;

    const int iters = K >> 5;   // BK=32

    #pragma unroll
    for (int s = 0; s < NSTG - 1; s++) {
        unsigned off = s * BSTG_WORDS * 4;
        int ko = s << 5;
        cp16(dA + off,      Ag + ko,     true);
        cp16(dA + off + 16, Ag + ko + 8, true);
        cp16(dB + off,      Wg + ko,     wok);
        cp16(dB + off + 16, Wg + ko + 8, wok);
        cp_commit();
    }

    int s = 0;
    for (int it = 0; it < iters; it++) {
        cp_wait2();
        __syncthreads();

        const unsigned* Asm = sh + s * BSTG_WORDS;
        const unsigned* Bsm = Asm + 2560;

        #pragma unroll
        for (int kb = 0; kb < 16; kb += 8) {     // two k16 blocks
            unsigned af[4][4], bf[4][2];
            #pragma unroll
            for (int mt = 0; mt < 4; mt++) {
                int m = wm*64 + mt*16 + grp;
                af[mt][0] = Asm[(m  )*20 + kb + t4];
                af[mt][1] = Asm[(m+8)*20 + kb + t4];
                af[mt][2] = Asm[(m  )*20 + kb + t4 + 4];
                af[mt][3] = Asm[(m+8)*20 + kb + t4 + 4];
            }
            #pragma unroll
            for (int nt = 0; nt < 4; nt++) {
                int n = wn*32 + nt*8 + grp;
                bf[nt][0] = Bsm[n*20 + kb + t4];
                bf[nt][1] = Bsm[n*20 + kb + t4 + 4];
            }
            #pragma unroll
            for (int mt = 0; mt < 4; mt++)
                #pragma unroll
                for (int nt = 0; nt < 4; nt++)
                    mma_bf16(acc[mt][nt], af[mt], bf[nt]);
        }

        int kt = it + NSTG - 1;
        if (kt < iters) {
            int sn = s + NSTG - 1; if (sn >= NSTG) sn -= NSTG;
            unsigned off = sn * BSTG_WORDS * 4;
            int ko = kt << 5;
            cp16(dA + off,      Ag + ko,     true);
            cp16(dA + off + 16, Ag + ko + 8, true);
            cp16(dB + off,      Wg + ko,     wok);
            cp16(dB + off + 16, Wg + ko + 8, wok);
        }
        cp_commit();
        if (++s == NSTG) s = 0;
    }

    #pragma unroll
    for (int mt = 0; mt < 4; mt++) {
        #pragma unroll
        for (int nt = 0; nt < 4; nt++) {
            int rbase = m0 + wm*64 + mt*16 + grp;
            int cbase = n0 + wn*32 + nt*8 + t4*2;
            #pragma unroll
            for (int rr = 0; rr < 2; rr++) {
                int m = rbase + rr*8;
                #pragma unroll
                for (int cc = 0; cc < 2; cc++) {
                    int n = cbase + cc;
                    if (n < N)
                        Co[(size_t)m*N + n] = __float2bfloat16(acc[mt][nt][rr*2 + cc] + bias[n]);
                }
            }
        }
    }
}

// ---------------- Flash self-attention (bf16 MMA, exp2 softmax) ----------
__global__ void __launch_bounds__(256) attn_mma(const float* __restrict__ qkv,
                                                float* __restrict__ out)
{
    __shared__ unsigned Ksp[64][20];
    __shared__ unsigned Vtp[32][36];

    const int bx = blockIdx.x;
    const int qt = bx & 7;
    const int h  = (bx >> 3) & 7;
    const int b  = bx >> 6;
    const int t = threadIdx.x, warp = t >> 5, lane = t & 31;
    const int grp = lane >> 2, t4 = lane & 3;
    const int q0 = qt*128, wq = warp*16;

    // 1/sqrt(32) * log2(e): softmax computed in base-2 domain
    const float scale = 0.17677669529663687f * 1.44269504088896340f;

    const float* qb = qkv + ((size_t)(b*NQ_ + q0 + wq))*768 + h*32;
    unsigned Qf[2][4];
    #pragma unroll
    for (int kb = 0; kb < 2; kb++) {
        int c0 = kb*16 + 2*t4;
        Qf[kb][0] = pack2(qb[(size_t)(grp  )*768 + c0    ]*scale, qb[(size_t)(grp  )*768 + c0 + 1]*scale);
        Qf[kb][1] = pack2(qb[(size_t)(grp+8)*768 + c0    ]*scale, qb[(size_t)(grp+8)*768 + c0 + 1]*scale);
        Qf[kb][2] = pack2(qb[(size_t)(grp  )*768 + c0 + 8]*scale, qb[(size_t)(grp  )*768 + c0 + 9]*scale);
        Qf[kb][3] = pack2(qb[(size_t)(grp+8)*768 + c0 + 8]*scale, qb[(size_t)(grp+8)*768 + c0 + 9]*scale);
    }

    float m_a = -1e30f, m_b = -1e30f, l_a = 0.f, l_b = 0.f;
    float oac[4][4];
    #pragma unroll
    for (int i = 0; i < 4; i++)
        #pragma unroll
        for (int j = 0; j < 4; j++) oac[i][j] = 0.f;

    const float* kg = qkv + (size_t)(b*NQ_)*768 + 256 + h*32;
    const float* vg = qkv + (size_t)(b*NQ_)*768 + 512 + h*32;

    const int lrow = t >> 2, lj = t & 3;
    const int sp = t >> 3, dg = (t & 7) * 4;

    for (int kt = 0; kt < 16; kt++) {
        __syncthreads();
        {
            const float* src = kg + (size_t)(kt*64 + lrow)*768 + lj*8;
            float4 v0 = *(const float4*)(src);
            float4 v1 = *(const float4*)(src + 4);
            uint4 w;
            w.x = pack2(v0.x, v0.y); w.y = pack2(v0.z, v0.w);
            w.z = pack2(v1.x, v1.y); w.w = pack2(v1.z, v1.w);
            *(uint4*)&Ksp[lrow][lj*4] = w;
            const float* sv = vg + (size_t)(kt*64 + 2*sp)*768 + dg;
            float4 a = *(const float4*)(sv);
            float4 c = *(const float4*)(sv + 768);
            Vtp[dg+0][sp] = pack2(a.x, c.x);
            Vtp[dg+1][sp] = pack2(a.y, c.y);
            Vtp[dg+2][sp] = pack2(a.z, c.z);
            Vtp[dg+3][sp] = pack2(a.w, c.w);
        }
        __syncthreads();

        float sacc[8][4];
        #pragma unroll
        for (int nt = 0; nt < 8; nt++)
            #pragma unroll
            for (int r = 0; r < 4; r++) sacc[nt][r] = 0.f;
        #pragma unroll
        for (int kb = 0; kb < 2; kb++) {
            #pragma unroll
            for (int nt = 0; nt < 8; nt++) {
                unsigned bf[2];
                bf[0] = Ksp[nt*8 + grp][kb*8 + t4];
                bf[1] = Ksp[nt*8 + grp][kb*8 + 4 + t4];
                mma_bf16(sacc[nt], Qf[kb], bf);
            }
        }

        float mx_a = -1e30f, mx_b = -1e30f;
        #pragma unroll
        for (int nt = 0; nt < 8; nt++) {
            mx_a = fmaxf(mx_a, fmaxf(sacc[nt][0], sacc[nt][1]));
            mx_b = fmaxf(mx_b, fmaxf(sacc[nt][2], sacc[nt][3]));
        }
        mx_a = fmaxf(mx_a, __shfl_xor_sync(0xffffffffu, mx_a, 1));
        mx_a = fmaxf(mx_a, __shfl_xor_sync(0xffffffffu, mx_a, 2));
        mx_b = fmaxf(mx_b, __shfl_xor_sync(0xffffffffu, mx_b, 1));
        mx_b = fmaxf(mx_b, __shfl_xor_sync(0xffffffffu, mx_b, 2));
        float mna = fmaxf(m_a, mx_a), mnb = fmaxf(m_b, mx_b);
        float ca = exp2f(m_a - mna), cb = exp2f(m_b - mnb);
        float sa = 0.f, sb = 0.f;
        #pragma unroll
        for (int nt = 0; nt < 8; nt++) {
            sacc[nt][0] = exp2f(sacc[nt][0] - mna);
            sacc[nt][1] = exp2f(sacc[nt][1] - mna);
            sacc[nt][2] = exp2f(sacc[nt][2] - mnb);
            sacc[nt][3] = exp2f(sacc[nt][3] - mnb);
            sa += sacc[nt][0] + sacc[nt][1];
            sb += sacc[nt][2] + sacc[nt][3];
        }
        sa += __shfl_xor_sync(0xffffffffu, sa, 1);
        sa += __shfl_xor_sync(0xffffffffu, sa, 2);
        sb += __shfl_xor_sync(0xffffffffu, sb, 1);
        sb += __shfl_xor_sync(0xffffffffu, sb, 2);
        l_a = l_a*ca + sa;  l_b = l_b*cb + sb;
        m_a = mna;          m_b = mnb;
        #pragma unroll
        for (int nt = 0; nt < 4; nt++) {
            oac[nt][0] *= ca; oac[nt][1] *= ca;
            oac[nt][2] *= cb; oac[nt][3] *= cb;
        }

        #pragma unroll
        for (int kb = 0; kb < 4; kb++) {
            unsigned pa[4];
            pa[0] = pack2(sacc[2*kb  ][0], sacc[2*kb  ][1]);
            pa[1] = pack2(sacc[2*kb  ][2], sacc[2*kb  ][3]);
            pa[2] = pack2(sacc[2*kb+1][0], sacc[2*kb+1][1]);
            pa[3] = pack2(sacc[2*kb+1][2], sacc[2*kb+1][3]);
            #pragma unroll
            for (int nt = 0; nt < 4; nt++) {
                unsigned bf[2];
                bf[0] = Vtp[nt*8 + grp][kb*8 + t4];
                bf[1] = Vtp[nt*8 + grp][kb*8 + 4 + t4];
                mma_bf16(oac[nt], pa, bf);
            }
        }
    }

    float inva = 1.f / l_a, invb = 1.f / l_b;
    float* ob = out + ((size_t)(b*NQ_ + q0 + wq))*C_ + h*32;
    #pragma unroll
    for (int nt = 0; nt < 4; nt++) {
        ob[(size_t)(grp  )*C_ + nt*8 + 2*t4    ] = oac[nt][0]*inva;
        ob[(size_t)(grp  )*C_ + nt*8 + 2*t4 + 1] = oac[nt][1]*inva;
        ob[(size_t)(grp+8)*C_ + nt*8 + 2*t4    ] = oac[nt][2]*invb;
        ob[(size_t)(grp+8)*C_ + nt*8 + 2*t4 + 1] = oac[nt][3]*invb;
    }
}

// ---------------- reference points: sigmoid(q @ ref_w^T + ref_b) ---------
__global__ void __launch_bounds__(256) ref_kernel(const float* __restrict__ q,
    const float* __restrict__ rw, const float* __restrict__ rb,
    float* __restrict__ outp)
{
    int wid = threadIdx.x >> 5, lane = threadIdx.x & 31;
    int row = blockIdx.x*8 + wid;
    const float* x = q + (size_t)row*C_;
    float s0 = 0.f, s1 = 0.f;
    #pragma unroll
    for (int i = 0; i < 8; i++) {
        float xv = x[lane + 32*i];
        s0 += xv * rw[lane + 32*i];
        s1 += xv * rw[C_ + lane + 32*i];
    }
    #pragma unroll
    for (int o = 16; o; o >>= 1) {
        s0 += __shfl_xor_sync(0xffffffffu, s0, o);
        s1 += __shfl_xor_sync(0xffffffffu, s1, o);
    }
    if (lane == 0) {
        outp[(size_t)row*2    ] = 1.f/(1.f + __expf(-(s0 + rb[0])));
        outp[(size_t)row*2 + 1] = 1.f/(1.f + __expf(-(s1 + rb[1])));
    }
}

// ---------------- MSDeformAttn sampling (bf16 value) ---------------------
__global__ void __launch_bounds__(256) msdeform_kernel(const __nv_bfloat16* __restrict__ value,
    const float* __restrict__ ref, const float* __restrict__ so,
    const float* __restrict__ aw, float* __restrict__ outp)
{
    const int wid = threadIdx.x >> 5, lane = threadIdx.x & 31;
    const int gw = blockIdx.x*8 + wid;
    const int h  = gw & 7;
    const int bq = gw >> 3;
    const int b  = bq >> 10;

    float logit = -1e30f;
    if (lane < 24) logit = aw[(size_t)bq*192 + h*24 + lane];
    float mx = logit;
    #pragma unroll
    for (int o = 16; o; o >>= 1) mx = fmaxf(mx, __shfl_xor_sync(0xffffffffu, mx, o));
    float e = (lane < 24) ? __expf(logit - mx) : 0.f;
    float ssum = e;
    #pragma unroll
    for (int o = 16; o; o >>= 1) ssum += __shfl_xor_sync(0xffffffffu, ssum, o);
    float pw = e / ssum;

    float offx = 0.f, offy = 0.f;
    if (lane < 24) {
        int l = lane >> 3, p = lane & 7;
        const float* sp = so + (size_t)bq*384 + ((size_t)((h*3 + l)*8 + p))*2;
        offx = sp[0]; offy = sp[1];
    }
    float rx = ref[(size_t)bq*2], ry = ref[(size_t)bq*2 + 1];

    const int HL[3] = {128, 64, 32};
    const int WL[3] = {128, 64, 32};
    const int ST[3] = {0, 16384, 20480};

    float acc = 0.f;
    #pragma unroll
    for (int l = 0; l < 3; l++) {
        const int h_l = HL[l], w_l = WL[l], start = ST[l];
        const float gxb = rx * (float)w_l - 0.5f;
        const float gyb = ry * (float)h_l - 0.5f;
        const __nv_bfloat16* vb = value + ((size_t)(b*S_ + start))*C_ + h*32 + lane;
        #pragma unroll
        for (int p = 0; p < 8; p++) {
            int lp = l*8 + p;
            float ox = __shfl_sync(0xffffffffu, offx, lp);
            float oy = __shfl_sync(0xffffffffu, offy, lp);
            float w  = __shfl_sync(0xffffffffu, pw,   lp);
            float gx = gxb + ox;
            float gy = gyb + oy;
            float x0f = floorf(gx), y0f = floorf(gy);
            float lx = gx - x0f, ly = gy - y0f;
            int x0 = (int)x0f, y0 = (int)y0f;
            float w00 = (1.f-lx)*(1.f-ly)*w;
            float w01 = lx*(1.f-ly)*w;
            float w10 = (1.f-lx)*ly*w;
            float w11 = lx*ly*w;
            bool vx0 = (x0   >= 0) & (x0   < w_l);
            bool vx1 = (x0+1 >= 0) & (x0+1 < w_l);
            if (y0 >= 0 && y0 < h_l) {
                const __nv_bfloat16* rowp = vb + (size_t)y0*w_l*C_;
                if (vx0) acc += w00 * __bfloat162float(rowp[(size_t)x0*C_]);
                if (vx1) acc += w01 * __bfloat162float(rowp[(size_t)(x0+1)*C_]);
            }
            if (y0+1 >= 0 && y0+1 < h_l) {
                const __nv_bfloat16* rowp = vb + (size_t)(y0+1)*w_l*C_;
                if (vx0) acc += w10 * __bfloat162float(rowp[(size_t)x0*C_]);
                if (vx1) acc += w11 * __bfloat162float(rowp[(size_t)(x0+1)*C_]);
            }
        }
    }
    outp[(size_t)bq*C_ + h*32 + lane] = acc;
}

// ---------------- launch ----------------
extern "C" void kernel_launch(void* const* d_in, const int* in_sizes, int n_in,
                              void* d_out, int out_size)
{
    const float* tgt    = (const float*)d_in[0];
    const float* memory = (const float*)d_in[1];
    const float* n1w = (const float*)d_in[2];
    const float* n1b = (const float*)d_in[3];
    const float* inw = (const float*)d_in[4];
    const float* inb = (const float*)d_in[5];
    const float* outw= (const float*)d_in[6];
    const float* outb= (const float*)d_in[7];
    const float* n2w = (const float*)d_in[8];
    const float* n2b = (const float*)d_in[9];
    const float* refw= (const float*)d_in[10];
    const float* refb= (const float*)d_in[11];
    const float* sow = (const float*)d_in[12];
    const float* sob = (const float*)d_in[13];
    const float* aww = (const float*)d_in[14];
    const float* awb = (const float*)d_in[15];
    const float* vpw = (const float*)d_in[16];
    const float* vpb = (const float*)d_in[17];
    const float* opw = (const float*)d_in[18];
    const float* opb = (const float*)d_in[19];
    const float* n3w = (const float*)d_in[20];
    const float* n3b = (const float*)d_in[21];
    const float* l1w = (const float*)d_in[22];
    const float* l1b = (const float*)d_in[23];
    const float* l2w = (const float*)d_in[24];
    const float* l2b = (const float*)d_in[25];

    float *q, *qkv, *attn, *tgt2, *tgt3, *so, *aw, *refo, *ca, *ff1;
    __nv_bfloat16 *valh, *memh, *vpwh;
    cudaGetSymbolAddress((void**)&q,    g_q);
    cudaGetSymbolAddress((void**)&qkv,  g_qkv);
    cudaGetSymbolAddress((void**)&attn, g_attn);
    cudaGetSymbolAddress((void**)&tgt2, g_tgt2);
    cudaGetSymbolAddress((void**)&tgt3, g_tgt3);
    cudaGetSymbolAddress((void**)&valh, g_valh);
    cudaGetSymbolAddress((void**)&memh, g_memh);
    cudaGetSymbolAddress((void**)&vpwh, g_vpwh);
    cudaGetSymbolAddress((void**)&so,   g_so);
    cudaGetSymbolAddress((void**)&aw,   g_aw);
    cudaGetSymbolAddress((void**)&refo, g_ref);
    cudaGetSymbolAddress((void**)&ca,   g_ca);
    cudaGetSymbolAddress((void**)&ff1,  g_ff1);

    static cudaStream_t s2 = 0;
    static cudaEvent_t evFork = 0, evJoin = 0;
    if (!s2) {
        cudaStreamCreateWithFlags(&s2, cudaStreamNonBlocking);
        cudaEventCreateWithFlags(&evFork, cudaEventDisableTiming);
        cudaEventCreateWithFlags(&evJoin, cudaEventDisableTiming);
        cudaFuncSetAttribute(gemm_tc<0>, cudaFuncAttributeMaxDynamicSharedMemorySize, SMEM_BYTES);
        cudaFuncSetAttribute(gemm_tc<1>, cudaFuncAttributeMaxDynamicSharedMemorySize, SMEM_BYTES);
        cudaFuncSetAttribute(gemm_bf,    cudaFuncAttributeMaxDynamicSharedMemorySize, BSMEM_BYTES);
    }

    // ---- fork: value path (convert + bf16 GEMM) on s2 ----
    cudaEventRecord(evFork, 0);
    cudaStreamWaitEvent(s2, evFork, 0);
    cvt2bf16<<<4096, 256, 0, s2>>>((const float4*)memory, (uint2*)memh, (long)BS_*C_/4);
    cvt2bf16<<<64,   256, 0, s2>>>((const float4*)vpw,    (uint2*)vpwh, (long)C_*C_/4);
    gemm_bf<<<dim3(C_/128, BS_/128), 256, BSMEM_BYTES, s2>>>(memh, vpwh, vpb, valh, BS_, C_, C_);
    cudaEventRecord(evJoin, s2);

    // ---- main chain (stream 0) ----
    ln_kernel<<<BNQ, 256>>>(tgt, n1w, n1b, q);
    gemm_tc<0><<<dim3(768/128, BNQ/128), 256, SMEM_BYTES>>>(q, inw, inb, nullptr, qkv, BNQ, 768, C_);
    attn_mma<<<B_*8*8, 256>>>(qkv, attn);
    gemm_tc<0><<<dim3(C_/128, BNQ/128), 256, SMEM_BYTES>>>(attn, outw, outb, tgt, tgt2, BNQ, C_, C_);
    ln_kernel<<<BNQ, 256>>>(tgt2, n2w, n2b, q);
    gemm_tc<0><<<dim3(3, BNQ/128), 256, SMEM_BYTES>>>(q, sow, sob, nullptr, so, BNQ, 384, C_);
    gemm_tc<0><<<dim3(2, BNQ/128), 256, SMEM_BYTES>>>(q, aww, awb, nullptr, aw, BNQ, 192, C_);
    ref_kernel<<<BNQ/8, 256>>>(q, refw, refb, refo);

    cudaStreamWaitEvent(0, evJoin, 0);

    msdeform_kernel<<<BNQ, 256>>>(valh, refo, so, aw, ca);
    gemm_tc<0><<<dim3(C_/128, BNQ/128), 256, SMEM_BYTES>>>(ca, opw, opb, tgt2, tgt3, BNQ, C_, C_);
    ln_kernel<<<BNQ, 256>>>(tgt3, n3w, n3b, q);
    gemm_tc<1><<<dim3(1024/128, BNQ/128), 256, SMEM_BYTES>>>(q, l1w, l1b, nullptr, ff1, BNQ, 1024, C_);
    gemm_tc<0><<<dim3(C_/128, BNQ/128), 256, SMEM_BYTES>>>(ff1, l2w, l2b, tgt3, (float*)d_out, BNQ, C_, 1024);
}